// round 1
// baseline (speedup 1.0000x reference)
#include <cuda_runtime.h>
#include <cuda_bf16.h>
#include <math.h>

// ---------------------------------------------------------------------------
// PPO fused loss on GB300.
// Inputs (metadata order):
//  0 states[T,512] f32, 1 next_states[T,512] f32, 2 rewards[T] f32,
//  3 dones[T] i32, 4 actions[T] i32, 5 log_probs[T] f32,
//  6 actor_w[512,64] f32, 7 actor_b[64] f32, 8 critic_w[512,1] f32, 9 critic_b[1] f32
// Output: [actor_loss, value_loss] f32
// ---------------------------------------------------------------------------

#define T_MAX   262144
#define S_DIM   512
#define A_DIM   64
#define BM      128
#define BK      32
#define THREADS 128
#define GAMMA_F 0.99f
#define LAM_F   0.98f
#define GL_F    (0.99f * 0.98f)
#define CLIP_LO 0.8f
#define CLIP_HI 1.2f
#define ENT_C   0.01f
#define CHUNK   2048          // scan chunk = 256 threads * 8 elems
#define NB_MAX  (T_MAX / CHUNK)

// scratch (allocation-free rule: device globals)
__device__ float g_delta[T_MAX];
__device__ float g_ratio[T_MAX];
__device__ float g_ent[T_MAX / BM];
__device__ float g_cA[NB_MAX];
__device__ float g_cB[NB_MAX];
__device__ float g_cx[NB_MAX];
__device__ float g_surr[NB_MAX];
__device__ float g_adv2[NB_MAX];

// ---- packed f32x2 helpers (sm_103a FFMA2 path, PTX-only) ------------------
__device__ __forceinline__ void ffma2(unsigned long long& d,
                                      unsigned long long a,
                                      unsigned long long b) {
    asm("fma.rn.f32x2 %0, %1, %2, %0;" : "+l"(d) : "l"(a), "l"(b));
}
__device__ __forceinline__ unsigned long long dup2(float x) {
    unsigned long long r;
    asm("mov.b64 %0, {%1, %2};" : "=l"(r) : "f"(x), "f"(x));
    return r;
}
__device__ __forceinline__ void unpack2(unsigned long long v, float& lo, float& hi) {
    asm("mov.b64 {%0, %1}, %2;" : "=f"(lo), "=f"(hi) : "l"(v));
}

// ---------------------------------------------------------------------------
// Kernel 1: fused GEMM (logits) + critic GEMVs + softmax stats.
// Writes g_delta[t], g_ratio[t], g_ent[block].
// ---------------------------------------------------------------------------
__global__ void __launch_bounds__(THREADS)
k1_main(const float* __restrict__ states,
        const float* __restrict__ next_states,
        const float* __restrict__ rewards,
        const int*   __restrict__ dones,
        const int*   __restrict__ actions,
        const float* __restrict__ log_probs,
        const float* __restrict__ actor_w,
        const float* __restrict__ actor_b,
        const float* __restrict__ critic_w,
        const float* __restrict__ critic_b) {
    // smem: A-tile transposed [k][row], odd stride 129 -> conflict-free STS and LDS
    __shared__ __align__(16) float sA[BK][BM + 1];
    __shared__ __align__(16) float sW[BK][A_DIM];
    __shared__ __align__(16) float scw[S_DIM];
    __shared__ float sv[BM];
    __shared__ float snv[BM];
    __shared__ float sEnt[16];

    const int tid  = threadIdx.x;
    const int lane = tid & 31;
    const int tx   = tid & 7;    // col group (8 cols)
    const int ty   = tid >> 3;   // row group (8 rows)
    const int row0 = blockIdx.x * BM;

    // stage critic_w (512 floats = 128 threads * float4)
    ((float4*)scw)[tid] = ((const float4*)critic_w)[tid];

    // actor bias for my 8 columns
    float bias[8];
    {
        float4 b0 = ((const float4*)actor_b)[tx * 2];
        float4 b1 = ((const float4*)actor_b)[tx * 2 + 1];
        bias[0] = b0.x; bias[1] = b0.y; bias[2] = b0.z; bias[3] = b0.w;
        bias[4] = b1.x; bias[5] = b1.y; bias[6] = b1.z; bias[7] = b1.w;
    }
    const float cb = critic_b[0];
    __syncthreads();

    // ---- prologue: next_values (warp-cooperative dot per row) ----
    {
        const int w = tid >> 5;               // warp id 0..3, handles 32 rows
        for (int i = 0; i < 32; ++i) {
            const int r = w * 32 + i;
            const float4* ns = (const float4*)(next_states + (size_t)(row0 + r) * S_DIM);
            float acc = 0.f;
#pragma unroll
            for (int it = 0; it < 4; ++it) {
                float4 x = ns[it * 32 + lane];
                float4 c = ((const float4*)scw)[it * 32 + lane];
                acc = fmaf(x.x, c.x, fmaf(x.y, c.y, fmaf(x.z, c.z, fmaf(x.w, c.w, acc))));
            }
#pragma unroll
            for (int o = 16; o > 0; o >>= 1)
                acc += __shfl_xor_sync(0xffffffffu, acc, o);
            if (lane == 0) snv[r] = acc + cb;
        }
    }

    // ---- main loop: C[8x8] accumulators as f32x2 pairs ----
    unsigned long long acc2[8][4];
#pragma unroll
    for (int j = 0; j < 8; ++j)
#pragma unroll
        for (int p = 0; p < 4; ++p) acc2[j][p] = 0ull;
    float vacc = 0.f;

    const int rr = tid >> 3;          // 0..15 (A-tile load row group)
    const int k0 = (tid & 7) * 4;     // 0..28 (A-tile load k base)

    for (int kb = 0; kb < S_DIM; kb += BK) {
        __syncthreads();
        // fill sW: 32x64 floats, coalesced
        const float4* wg = (const float4*)(actor_w + (size_t)kb * A_DIM);
#pragma unroll
        for (int p = 0; p < 4; ++p)
            ((float4*)&sW[0][0])[p * 128 + tid] = wg[p * 128 + tid];
        // fill sA transposed: 8 passes of 16 rows; coalesced LDG.128, conflict-free STS
#pragma unroll
        for (int p = 0; p < 8; ++p) {
            const int r = p * 16 + rr;
            float4 x = *(const float4*)(states + (size_t)(row0 + r) * S_DIM + kb + k0);
            sA[k0 + 0][r] = x.x;
            sA[k0 + 1][r] = x.y;
            sA[k0 + 2][r] = x.z;
            sA[k0 + 3][r] = x.w;
        }
        __syncthreads();

#pragma unroll 8
        for (int k = 0; k < BK; ++k) {
            ulonglong2 bl0 = *(const ulonglong2*)&sW[k][tx * 8];
            ulonglong2 bl1 = *(const ulonglong2*)&sW[k][tx * 8 + 4];
            // critic partial from the same staged A tile (row = tid)
            vacc = fmaf(sA[k][tid], scw[kb + k], vacc);
#pragma unroll
            for (int j = 0; j < 8; ++j) {
                unsigned long long ad = dup2(sA[k][ty * 8 + j]);
                ffma2(acc2[j][0], ad, bl0.x);
                ffma2(acc2[j][1], ad, bl0.y);
                ffma2(acc2[j][2], ad, bl1.x);
                ffma2(acc2[j][3], ad, bl1.y);
            }
        }
    }
    sv[tid] = vacc + cb;
    __syncthreads();

    // ---- epilogue: per-row softmax stats via 8-lane shuffle groups ----
    float entLocal = 0.f;
#pragma unroll
    for (int j = 0; j < 8; ++j) {
        float l[8];
#pragma unroll
        for (int p = 0; p < 4; ++p) {
            float lo, hi;
            unpack2(acc2[j][p], lo, hi);
            l[2 * p]     = lo + bias[2 * p];
            l[2 * p + 1] = hi + bias[2 * p + 1];
        }
        float m = l[0];
#pragma unroll
        for (int c = 1; c < 8; ++c) m = fmaxf(m, l[c]);
#pragma unroll
        for (int o = 1; o < 8; o <<= 1)
            m = fmaxf(m, __shfl_xor_sync(0xffffffffu, m, o));
        float se = 0.f, pe = 0.f;
#pragma unroll
        for (int c = 0; c < 8; ++c) {
            float t = l[c] - m;
            float e = expf(t);
            se += e;
            pe = fmaf(e, t, pe);
        }
#pragma unroll
        for (int o = 1; o < 8; o <<= 1) {
            se += __shfl_xor_sync(0xffffffffu, se, o);
            pe += __shfl_xor_sync(0xffffffffu, pe, o);
        }
        const float logse = logf(se);
        const int grow = row0 + ty * 8 + j;
        const int a = actions[grow];
        float cand = l[a & 7];
        float la = __shfl_sync(0xffffffffu, cand, (lane & 24) | (a >> 3));
        if (tx == 0) {
            const float new_lp = la - m - logse;
            const float ratio  = expf(new_lp - log_probs[grow]);
            const float nd     = 1.f - (float)dones[grow];
            const float v  = sv[ty * 8 + j];
            const float nv = snv[ty * 8 + j];
            g_delta[grow] = rewards[grow] + GAMMA_F * nv * nd - v;
            g_ratio[grow] = ratio;
            entLocal += (logse - pe / se);
        }
    }
    if (tx == 0) sEnt[ty] = entLocal;
    __syncthreads();
    if (tid == 0) {
        float s = 0.f;
#pragma unroll
        for (int i = 0; i < 16; ++i) s += sEnt[i];
        g_ent[blockIdx.x] = s;
    }
}

// ---------------------------------------------------------------------------
// GAE scan: adv_t = d_t + c_t * adv_{t+1}, reverse.  Affine composition:
// combine(left, right) = (a_l*a_r, b_l + a_l*b_r), left = lower index.
// ---------------------------------------------------------------------------
__device__ __forceinline__ void thread_affine(const int* __restrict__ dones,
                                              int base, float (&d)[8], float (&c)[8],
                                              float& A, float& Bv) {
    float4 d0 = *(const float4*)&g_delta[base];
    float4 d1 = *(const float4*)&g_delta[base + 4];
    int4 q0 = *(const int4*)&dones[base];
    int4 q1 = *(const int4*)&dones[base + 4];
    d[0]=d0.x; d[1]=d0.y; d[2]=d0.z; d[3]=d0.w;
    d[4]=d1.x; d[5]=d1.y; d[6]=d1.z; d[7]=d1.w;
    c[0]=GL_F*(1.f-(float)q0.x); c[1]=GL_F*(1.f-(float)q0.y);
    c[2]=GL_F*(1.f-(float)q0.z); c[3]=GL_F*(1.f-(float)q0.w);
    c[4]=GL_F*(1.f-(float)q1.x); c[5]=GL_F*(1.f-(float)q1.y);
    c[6]=GL_F*(1.f-(float)q1.z); c[7]=GL_F*(1.f-(float)q1.w);
    A = 1.f; Bv = 0.f;
#pragma unroll
    for (int j = 7; j >= 0; --j) {   // compose f_j on the left
        Bv = fmaf(c[j], Bv, d[j]);
        A  = c[j] * A;
    }
}

__global__ void __launch_bounds__(256)
k2_chunk_reduce(const int* __restrict__ dones) {
    __shared__ float sa[256], sb[256];
    const int tid = threadIdx.x;
    const int base = blockIdx.x * CHUNK + tid * 8;
    float d[8], c[8], A, Bv;
    thread_affine(dones, base, d, c, A, Bv);
    sa[tid] = A; sb[tid] = Bv;
    __syncthreads();
    for (int s = 1; s < 256; s <<= 1) {
        if ((tid & (2 * s - 1)) == 0) {
            float al = sa[tid], bl = sb[tid];
            float ar = sa[tid + s], br = sb[tid + s];
            sa[tid] = al * ar;
            sb[tid] = fmaf(al, br, bl);
        }
        __syncthreads();
    }
    if (tid == 0) { g_cA[blockIdx.x] = sa[0]; g_cB[blockIdx.x] = sb[0]; }
}

__global__ void k3_combine(int nb) {
    if (threadIdx.x == 0 && blockIdx.x == 0) {
        float x = 0.f;
        for (int b = nb - 1; b >= 0; --b) {
            g_cx[b] = x;                 // adv entering chunk b from the right
            x = fmaf(g_cA[b], x, g_cB[b]); // adv at chunk b start
        }
    }
}

__global__ void __launch_bounds__(256)
k4_apply(const int* __restrict__ dones) {
    __shared__ float sa[256], sb[256];
    const int tid = threadIdx.x;
    const int base = blockIdx.x * CHUNK + tid * 8;
    float d[8], c[8], A, Bv;
    thread_affine(dones, base, d, c, A, Bv);
    // Hillis-Steele suffix scan (inclusive) over thread composites
    sa[tid] = A; sb[tid] = Bv;
    __syncthreads();
    for (int dd = 1; dd < 256; dd <<= 1) {
        float al = sa[tid], bl = sb[tid];
        float ar = 1.f, br = 0.f;
        if (tid + dd < 256) { ar = sa[tid + dd]; br = sb[tid + dd]; }
        __syncthreads();
        sa[tid] = al * ar;
        sb[tid] = fmaf(al, br, bl);
        __syncthreads();
    }
    const float xb = g_cx[blockIdx.x];
    float xin = (tid == 255) ? xb : fmaf(sa[tid + 1], xb, sb[tid + 1]);

    float4 r0 = *(const float4*)&g_ratio[base];
    float4 r1 = *(const float4*)&g_ratio[base + 4];
    float rt[8] = {r0.x, r0.y, r0.z, r0.w, r1.x, r1.y, r1.z, r1.w};

    float adv = xin, s1 = 0.f, s2 = 0.f;
#pragma unroll
    for (int j = 7; j >= 0; --j) {
        adv = fmaf(c[j], adv, d[j]);
        const float r = rt[j];
        const float rc = fminf(fmaxf(r, CLIP_LO), CLIP_HI);
        s1 += fminf(r * adv, rc * adv);
        s2 = fmaf(adv, adv, s2);
    }
    __syncthreads();
    sa[tid] = s1; sb[tid] = s2;
    __syncthreads();
    for (int s = 128; s > 0; s >>= 1) {
        if (tid < s) { sa[tid] += sa[tid + s]; sb[tid] += sb[tid + s]; }
        __syncthreads();
    }
    if (tid == 0) { g_surr[blockIdx.x] = sa[0]; g_adv2[blockIdx.x] = sb[0]; }
}

__global__ void __launch_bounds__(256)
k5_final(float* __restrict__ out, int T, int nb, int nb1) {
    __shared__ float se_[256], ss_[256], sv_[256];
    const int tid = threadIdx.x;
    float e = 0.f, s = 0.f, v = 0.f;
    for (int i = tid; i < nb1; i += 256) e += g_ent[i];
    for (int i = tid; i < nb; i += 256) { s += g_surr[i]; v += g_adv2[i]; }
    se_[tid] = e; ss_[tid] = s; sv_[tid] = v;
    __syncthreads();
    for (int st = 128; st > 0; st >>= 1) {
        if (tid < st) {
            se_[tid] += se_[tid + st];
            ss_[tid] += ss_[tid + st];
            sv_[tid] += sv_[tid + st];
        }
        __syncthreads();
    }
    if (tid == 0) {
        const float invT = 1.f / (float)T;
        out[0] = -(ss_[0] * invT) - ENT_C * (se_[0] * invT);
        out[1] = sv_[0] * invT;
    }
}

extern "C" void kernel_launch(void* const* d_in, const int* in_sizes, int n_in,
                              void* d_out, int out_size) {
    const float* states      = (const float*)d_in[0];
    const float* next_states = (const float*)d_in[1];
    const float* rewards     = (const float*)d_in[2];
    const int*   dones       = (const int*)  d_in[3];
    const int*   actions     = (const int*)  d_in[4];
    const float* log_probs   = (const float*)d_in[5];
    const float* actor_w     = (const float*)d_in[6];
    const float* actor_b     = (const float*)d_in[7];
    const float* critic_w    = (const float*)d_in[8];
    const float* critic_b    = (const float*)d_in[9];
    float* out = (float*)d_out;

    const int T = in_sizes[2];
    const int nb1 = T / BM;      // 2048 main blocks
    const int nb  = T / CHUNK;   // 128 scan chunks

    k1_main<<<nb1, THREADS>>>(states, next_states, rewards, dones, actions,
                              log_probs, actor_w, actor_b, critic_w, critic_b);
    k2_chunk_reduce<<<nb, 256>>>(dones);
    k3_combine<<<1, 32>>>(nb);
    k4_apply<<<nb, 256>>>(dones);
    k5_final<<<1, 256>>>(out, T, nb, nb1);
}

// round 3
// speedup vs baseline: 1.2812x; 1.2812x over previous
#include <cuda_runtime.h>
#include <math.h>
#include <stdint.h>

// ---------------------------------------------------------------------------
// PPO fused loss on GB300 — mma.sync tf32 (arch-portable HMMA) actor GEMM,
// fp32 critic streams, blocked-scan GAE.
// ---------------------------------------------------------------------------

#define T_MAX   262144
#define S_DIM   512
#define A_DIM   64
#define BM      128
#define GAMMA_F 0.99f
#define GL_F    (0.99f * 0.98f)
#define CLIP_LO 0.8f
#define CLIP_HI 1.2f
#define ENT_C   0.01f
#define CHUNK   2048
#define NB_MAX  (T_MAX / CHUNK)

// scratch
__device__ float g_delta[T_MAX];
__device__ float g_ratio[T_MAX];
__device__ float g_ent[T_MAX / BM];
__device__ float g_cA[NB_MAX];
__device__ float g_cB[NB_MAX];
__device__ float g_cx[NB_MAX];
__device__ float g_surr[NB_MAX];
__device__ float g_adv2[NB_MAX];
// B fragments in exact m16n8k8 order: [64 ksteps][8 ngroups][32 lanes] float2
__device__ __align__(16) float2 g_wfrag[64 * 8 * 32];

// ---------------- smem layout ----------------
#define SLABS        16
#define RING         4
#define A_ROW_F      36                    // 32 floats + 4 pad (144 B rows)
#define A_SLAB_BYTES (128 * 144)           // 18432
#define WF_BYTES     (64 * 8 * 32 * 8)     // 131072
#define OFF_A    0
#define OFF_WF   (RING * A_SLAB_BYTES)     // 73728
#define OFF_SCW  (OFF_WF + WF_BYTES)       // 204800
#define OFF_SV   (OFF_SCW + 2048)          // 206848
#define OFF_SNV  (OFF_SV + 512)            // 207360
#define OFF_ENT  (OFF_SNV + 512)           // 207872
#define SMEM_TOTAL (OFF_ENT + 64)          // 207936
#define LOG_STRIDE 66                      // logits epilogue stride (reuses A ring)

// ---------------- PTX helpers ----------------
__device__ __forceinline__ uint32_t smem_to_u32(const void* p) {
    uint32_t a;
    asm("{ .reg .u64 t; cvta.to.shared.u64 t, %1; cvt.u32.u64 %0, t; }" : "=r"(a) : "l"(p));
    return a;
}
__device__ __forceinline__ void cpa16(uint32_t dst, const void* src) {
    asm volatile("cp.async.cg.shared.global [%0], [%1], 16;" :: "r"(dst), "l"(src) : "memory");
}
#define CP_COMMIT() asm volatile("cp.async.commit_group;" ::: "memory")
#define CP_WAIT2()  asm volatile("cp.async.wait_group 2;" ::: "memory")

__device__ __forceinline__ void mma_tf32(float (&d)[4], const uint32_t (&a)[4],
                                         const uint32_t (&b)[2]) {
    asm volatile(
        "mma.sync.aligned.m16n8k8.row.col.f32.tf32.tf32.f32 "
        "{%0,%1,%2,%3}, {%4,%5,%6,%7}, {%8,%9}, {%0,%1,%2,%3};"
        : "+f"(d[0]), "+f"(d[1]), "+f"(d[2]), "+f"(d[3])
        : "r"(a[0]), "r"(a[1]), "r"(a[2]), "r"(a[3]), "r"(b[0]), "r"(b[1]));
}
__device__ __forceinline__ uint32_t to_tf32(float x) {
    uint32_t r;
    asm("cvt.rna.tf32.f32 %0, %1;" : "=r"(r) : "f"(x));
    return r;
}

// ---------------------------------------------------------------------------
// prep: pack actor_w [512,64] into mma B-fragment order, tf32-rounded.
// entry e: lane=e&31, G=(e>>5)&7, ks=e>>8 ; n=G*8+(lane>>2), k=ks*8+(lane&3)
// ---------------------------------------------------------------------------
__global__ void kprep(const float* __restrict__ aw) {
    int e = blockIdx.x * 256 + threadIdx.x;      // 16384 entries
    int lane = e & 31, G = (e >> 5) & 7, ks = e >> 8;
    int n = G * 8 + (lane >> 2);
    int k = ks * 8 + (lane & 3);
    float2 v;
    v.x = __uint_as_float(to_tf32(aw[k * A_DIM + n]));
    v.y = __uint_as_float(to_tf32(aw[(k + 4) * A_DIM + n]));
    g_wfrag[e] = v;
}

// ---------------------------------------------------------------------------
// slab loader: states rows [row0,row0+128), cols [32s,32s+32) -> ring buf s&3
// 1024 granules of 16B, 256 threads x 4.
// ---------------------------------------------------------------------------
__device__ __forceinline__ void issue_slab(uint32_t su, int s,
                                           const float* __restrict__ states,
                                           int row0, int tid) {
    const uint32_t abase = su + OFF_A + (s & 3) * A_SLAB_BYTES;
    const float* asrc = states + (size_t)row0 * S_DIM + s * 32;
#pragma unroll
    for (int i = 0; i < 4; ++i) {
        int g = tid + i * 256;
        int r = g >> 3, u = g & 7;
        cpa16(abase + r * 144 + u * 16, asrc + (size_t)r * S_DIM + u * 4);
    }
}

// ---------------------------------------------------------------------------
// Main fused kernel
// ---------------------------------------------------------------------------
__global__ void __launch_bounds__(256, 1)
k1_mma(const float* __restrict__ states,
       const float* __restrict__ next_states,
       const float* __restrict__ rewards,
       const int*   __restrict__ dones,
       const int*   __restrict__ actions,
       const float* __restrict__ log_probs,
       const float* __restrict__ actor_b,
       const float* __restrict__ critic_w,
       const float* __restrict__ critic_b) {
    extern __shared__ __align__(16) char smem[];
    const uint32_t su = smem_to_u32(smem);
    const int tid  = threadIdx.x;
    const int wid  = tid >> 5;
    const int lane = tid & 31;
    const int q = lane >> 2, j = lane & 3;     // mma fragment coords
    const int wm = wid >> 1, wn = wid & 1;     // warp tile: rows wm*32.., cols wn*32..
    const int row0 = blockIdx.x * BM;

    float* scw  = (float*)(smem + OFF_SCW);
    float* sv   = (float*)(smem + OFF_SV);
    float* snv  = (float*)(smem + OFF_SNV);
    float* sEnt = (float*)(smem + OFF_ENT);

    if (tid < 128) ((float4*)scw)[tid] = ((const float4*)critic_w)[tid];
    const float cb = critic_b[0];

    // per-thread bias for the 8 columns this thread's D fragments own
    float bcol[8];
#pragma unroll
    for (int g = 0; g < 4; ++g) {
        const int c = wn * 32 + g * 8 + j * 2;
        bcol[2 * g]     = __ldg(actor_b + c);
        bcol[2 * g + 1] = __ldg(actor_b + c + 1);
    }

    // stage W fragments into smem (one group), then prefetch 3 A slabs
    {
        const char* wsrc = (const char*)g_wfrag;
#pragma unroll
        for (int i = 0; i < 32; ++i) {
            int g = tid + i * 256;
            cpa16(su + OFF_WF + g * 16, wsrc + (size_t)g * 16);
        }
        CP_COMMIT();
    }
#pragma unroll
    for (int s = 0; s < 3; ++s) { issue_slab(su, s, states, row0, tid); CP_COMMIT(); }

    float acc[2][4][4];
#pragma unroll
    for (int mt = 0; mt < 2; ++mt)
#pragma unroll
        for (int g = 0; g < 4; ++g)
#pragma unroll
            for (int p = 0; p < 4; ++p) acc[mt][g][p] = 0.f;

    const int rbase = wid * 16;
    float vacc[16], nvacc[16];
#pragma unroll
    for (int i = 0; i < 16; ++i) { vacc[i] = 0.f; nvacc[i] = 0.f; }

    const float2* wf = (const float2*)(smem + OFF_WF);

    for (int s = 0; s < SLABS; ++s) {
        CP_WAIT2();
        __syncthreads();
        if (s + 3 < SLABS) issue_slab(su, s + 3, states, row0, tid);
        CP_COMMIT();

        const float* Ab = (const float*)(smem + OFF_A + (size_t)(s & 3) * A_SLAB_BYTES);
        const float* Ar = Ab + (wm * 32 + q) * A_ROW_F + j;

        // tensor-core path: 4 ksteps x (2 m-tiles x 4 n-groups)
#pragma unroll
        for (int ks = 0; ks < 4; ++ks) {
            uint32_t bf[4][2];
#pragma unroll
            for (int g = 0; g < 4; ++g) {
                float2 v = wf[((s * 4 + ks) * 8 + wn * 4 + g) * 32 + lane];
                bf[g][0] = __float_as_uint(v.x);
                bf[g][1] = __float_as_uint(v.y);
            }
#pragma unroll
            for (int mt = 0; mt < 2; ++mt) {
                uint32_t af[4];
                const float* Am = Ar + mt * 16 * A_ROW_F + ks * 8;
                af[0] = __float_as_uint(Am[0]);
                af[1] = __float_as_uint(Am[8 * A_ROW_F]);
                af[2] = __float_as_uint(Am[4]);
                af[3] = __float_as_uint(Am[8 * A_ROW_F + 4]);
#pragma unroll
                for (int g = 0; g < 4; ++g) mma_tf32(acc[mt][g], af, bf[g]);
            }
        }

        // fp32 critic: values from staged slab, next_values streamed
        const float wn_c = scw[s * 32 + lane];
#pragma unroll
        for (int rr = 0; rr < 16; ++rr) {
            const int r = rbase + rr;
            vacc[rr] = fmaf(Ab[r * A_ROW_F + lane], wn_c, vacc[rr]);
            float nsv = __ldg(next_states + (size_t)(row0 + r) * S_DIM + s * 32 + lane);
            nvacc[rr] = fmaf(nsv, wn_c, nvacc[rr]);
        }
    }

    // reduce critic accumulators across lanes
#pragma unroll
    for (int rr = 0; rr < 16; ++rr) {
        float v = vacc[rr], n = nvacc[rr];
#pragma unroll
        for (int o = 16; o > 0; o >>= 1) {
            v += __shfl_xor_sync(0xffffffffu, v, o);
            n += __shfl_xor_sync(0xffffffffu, n, o);
        }
        if (lane == rr) { sv[rbase + rr] = v + cb; snv[rbase + rr] = n + cb; }
    }
    __syncthreads();

    // dump logits (+bias) into smem, reusing the A ring
    float* slog = (float*)(smem + OFF_A);
#pragma unroll
    for (int mt = 0; mt < 2; ++mt) {
        const int r = wm * 32 + mt * 16 + q;
#pragma unroll
        for (int g = 0; g < 4; ++g) {
            const int c = wn * 32 + g * 8 + j * 2;
            float2 lo = make_float2(acc[mt][g][0] + bcol[2 * g], acc[mt][g][1] + bcol[2 * g + 1]);
            float2 hi = make_float2(acc[mt][g][2] + bcol[2 * g], acc[mt][g][3] + bcol[2 * g + 1]);
            *(float2*)&slog[r * LOG_STRIDE + c] = lo;
            *(float2*)&slog[(r + 8) * LOG_STRIDE + c] = hi;
        }
    }
    __syncthreads();

    // softmax / ratio / delta / entropy: warps 0..3, one row per lane
    if (wid < 4) {
        const int r = wid * 32 + lane;
        const int grow = row0 + r;
        const float* lr = &slog[r * LOG_STRIDE];
        float m = -1e30f;
#pragma unroll
        for (int c = 0; c < A_DIM; ++c) m = fmaxf(m, lr[c]);
        const int a = actions[grow];
        float se = 0.f, pe = 0.f;
#pragma unroll
        for (int c = 0; c < A_DIM; ++c) {
            float t = lr[c] - m;
            float e = __expf(t);
            se += e;
            pe = fmaf(e, t, pe);
        }
        const float la = lr[a] - m;
        const float logse = __logf(se);
        const float ratio = __expf(la - logse - log_probs[grow]);
        const float nd = 1.f - (float)dones[grow];
        g_delta[grow] = rewards[grow] + GAMMA_F * snv[r] * nd - sv[r];
        g_ratio[grow] = ratio;
        float ent = logse - pe / se;
#pragma unroll
        for (int o = 16; o > 0; o >>= 1) ent += __shfl_xor_sync(0xffffffffu, ent, o);
        if (lane == 0) sEnt[wid] = ent;
    }
    __syncthreads();
    if (tid == 0) g_ent[blockIdx.x] = sEnt[0] + sEnt[1] + sEnt[2] + sEnt[3];
}

// ---------------------------------------------------------------------------
// GAE scan (unchanged, proven in round 1)
// ---------------------------------------------------------------------------
__device__ __forceinline__ void thread_affine(const int* __restrict__ dones,
                                              int base, float (&d)[8], float (&c)[8],
                                              float& A, float& Bv) {
    float4 d0 = *(const float4*)&g_delta[base];
    float4 d1 = *(const float4*)&g_delta[base + 4];
    int4 q0 = *(const int4*)&dones[base];
    int4 q1 = *(const int4*)&dones[base + 4];
    d[0]=d0.x; d[1]=d0.y; d[2]=d0.z; d[3]=d0.w;
    d[4]=d1.x; d[5]=d1.y; d[6]=d1.z; d[7]=d1.w;
    c[0]=GL_F*(1.f-(float)q0.x); c[1]=GL_F*(1.f-(float)q0.y);
    c[2]=GL_F*(1.f-(float)q0.z); c[3]=GL_F*(1.f-(float)q0.w);
    c[4]=GL_F*(1.f-(float)q1.x); c[5]=GL_F*(1.f-(float)q1.y);
    c[6]=GL_F*(1.f-(float)q1.z); c[7]=GL_F*(1.f-(float)q1.w);
    A = 1.f; Bv = 0.f;
#pragma unroll
    for (int jj = 7; jj >= 0; --jj) { Bv = fmaf(c[jj], Bv, d[jj]); A = c[jj] * A; }
}

__global__ void __launch_bounds__(256)
k2_chunk_reduce(const int* __restrict__ dones) {
    __shared__ float sa[256], sb[256];
    const int tid = threadIdx.x;
    const int base = blockIdx.x * CHUNK + tid * 8;
    float d[8], c[8], A, Bv;
    thread_affine(dones, base, d, c, A, Bv);
    sa[tid] = A; sb[tid] = Bv;
    __syncthreads();
    for (int s = 1; s < 256; s <<= 1) {
        if ((tid & (2 * s - 1)) == 0) {
            float al = sa[tid], bl = sb[tid];
            float ar = sa[tid + s], br = sb[tid + s];
            sa[tid] = al * ar;
            sb[tid] = fmaf(al, br, bl);
        }
        __syncthreads();
    }
    if (tid == 0) { g_cA[blockIdx.x] = sa[0]; g_cB[blockIdx.x] = sb[0]; }
}

__global__ void k3_combine(int nb) {
    if (threadIdx.x == 0 && blockIdx.x == 0) {
        float x = 0.f;
        for (int b = nb - 1; b >= 0; --b) {
            g_cx[b] = x;
            x = fmaf(g_cA[b], x, g_cB[b]);
        }
    }
}

__global__ void __launch_bounds__(256)
k4_apply(const int* __restrict__ dones) {
    __shared__ float sa[256], sb[256];
    const int tid = threadIdx.x;
    const int base = blockIdx.x * CHUNK + tid * 8;
    float d[8], c[8], A, Bv;
    thread_affine(dones, base, d, c, A, Bv);
    sa[tid] = A; sb[tid] = Bv;
    __syncthreads();
    for (int dd = 1; dd < 256; dd <<= 1) {
        float al = sa[tid], bl = sb[tid];
        float ar = 1.f, br = 0.f;
        if (tid + dd < 256) { ar = sa[tid + dd]; br = sb[tid + dd]; }
        __syncthreads();
        sa[tid] = al * ar;
        sb[tid] = fmaf(al, br, bl);
        __syncthreads();
    }
    const float xb = g_cx[blockIdx.x];
    float xin = (tid == 255) ? xb : fmaf(sa[tid + 1], xb, sb[tid + 1]);

    float4 r0 = *(const float4*)&g_ratio[base];
    float4 r1 = *(const float4*)&g_ratio[base + 4];
    float rt[8] = {r0.x, r0.y, r0.z, r0.w, r1.x, r1.y, r1.z, r1.w};

    float adv = xin, s1 = 0.f, s2 = 0.f;
#pragma unroll
    for (int jj = 7; jj >= 0; --jj) {
        adv = fmaf(c[jj], adv, d[jj]);
        const float r = rt[jj];
        const float rc = fminf(fmaxf(r, CLIP_LO), CLIP_HI);
        s1 += fminf(r * adv, rc * adv);
        s2 = fmaf(adv, adv, s2);
    }
    __syncthreads();
    sa[tid] = s1; sb[tid] = s2;
    __syncthreads();
    for (int s = 128; s > 0; s >>= 1) {
        if (tid < s) { sa[tid] += sa[tid + s]; sb[tid] += sb[tid + s]; }
        __syncthreads();
    }
    if (tid == 0) { g_surr[blockIdx.x] = sa[0]; g_adv2[blockIdx.x] = sb[0]; }
}

__global__ void __launch_bounds__(256)
k5_final(float* __restrict__ out, int T, int nb, int nb1) {
    __shared__ float se_[256], ss_[256], sv_[256];
    const int tid = threadIdx.x;
    float e = 0.f, s = 0.f, v = 0.f;
    for (int i = tid; i < nb1; i += 256) e += g_ent[i];
    for (int i = tid; i < nb; i += 256) { s += g_surr[i]; v += g_adv2[i]; }
    se_[tid] = e; ss_[tid] = s; sv_[tid] = v;
    __syncthreads();
    for (int st = 128; st > 0; st >>= 1) {
        if (tid < st) {
            se_[tid] += se_[tid + st];
            ss_[tid] += ss_[tid + st];
            sv_[tid] += sv_[tid + st];
        }
        __syncthreads();
    }
    if (tid == 0) {
        const float invT = 1.f / (float)T;
        out[0] = -(ss_[0] * invT) - ENT_C * (se_[0] * invT);
        out[1] = sv_[0] * invT;
    }
}

extern "C" void kernel_launch(void* const* d_in, const int* in_sizes, int n_in,
                              void* d_out, int out_size) {
    const float* states      = (const float*)d_in[0];
    const float* next_states = (const float*)d_in[1];
    const float* rewards     = (const float*)d_in[2];
    const int*   dones       = (const int*)  d_in[3];
    const int*   actions     = (const int*)  d_in[4];
    const float* log_probs   = (const float*)d_in[5];
    const float* actor_w     = (const float*)d_in[6];
    const float* actor_b     = (const float*)d_in[7];
    const float* critic_w    = (const float*)d_in[8];
    const float* critic_b    = (const float*)d_in[9];
    float* out = (float*)d_out;

    const int T   = in_sizes[2];
    const int nb1 = T / BM;       // 2048
    const int nb  = T / CHUNK;    // 128

    static int configured = 0;
    if (!configured) {
        cudaFuncSetAttribute(k1_mma, cudaFuncAttributeMaxDynamicSharedMemorySize, SMEM_TOTAL);
        configured = 1;
    }

    kprep<<<64, 256>>>(actor_w);
    k1_mma<<<nb1, 256, SMEM_TOTAL>>>(states, next_states, rewards, dones, actions,
                                     log_probs, actor_b, critic_w, critic_b);
    k2_chunk_reduce<<<nb, 256>>>(dones);
    k3_combine<<<1, 32>>>(nb);
    k4_apply<<<nb, 256>>>(dones);
    k5_final<<<1, 256>>>(out, T, nb, nb1);
}

// round 4
// speedup vs baseline: 1.4934x; 1.1656x over previous
#include <cuda_runtime.h>
#include <math.h>
#include <stdint.h>

// ---------------------------------------------------------------------------
// PPO fused loss on GB300 — mma.sync tf32 actor GEMM + tf32 tensor-core critic
// (critic_w as B column group 8), full cp.async streaming, blocked-scan GAE.
// ---------------------------------------------------------------------------

#define T_MAX   262144
#define S_DIM   512
#define A_DIM   64
#define BM      128
#define GAMMA_F 0.99f
#define GL_F    (0.99f * 0.98f)
#define CLIP_LO 0.8f
#define CLIP_HI 1.2f
#define ENT_C   0.01f
#define CHUNK   2048
#define NB_MAX  (T_MAX / CHUNK)
#define NGRP    9                          // 8 actor col-groups + 1 critic group

// scratch
__device__ float g_delta[T_MAX];
__device__ float g_ratio[T_MAX];
__device__ float g_ent[T_MAX / BM];
__device__ float g_cA[NB_MAX];
__device__ float g_cB[NB_MAX];
__device__ float g_surr[NB_MAX];
__device__ float g_adv2[NB_MAX];
// B fragments: [64 ksteps][9 groups][32 lanes] float2 (tf32-rounded)
__device__ __align__(16) float2 g_wfrag[64 * NGRP * 32];

// ---------------- smem layout ----------------
#define SLABS        16
#define RING         3
#define A_ROW_F      36                     // 32 floats + 4 pad (144 B rows)
#define SLAB_BYTES   (128 * 144)            // 18432
#define STAGE_BYTES  (2 * SLAB_BYTES)       // A + N = 36864
#define OFF_RING 0
#define OFF_SV   (RING * STAGE_BYTES)       // 110592
#define OFF_SNV  (OFF_SV + 512)
#define OFF_ENT  (OFF_SNV + 512)
#define SMEM_TOTAL (OFF_ENT + 64)           // 111680
#define LOG_STRIDE 66

// ---------------- PTX helpers ----------------
__device__ __forceinline__ uint32_t smem_to_u32(const void* p) {
    uint32_t a;
    asm("{ .reg .u64 t; cvta.to.shared.u64 t, %1; cvt.u32.u64 %0, t; }" : "=r"(a) : "l"(p));
    return a;
}
__device__ __forceinline__ void cpa16(uint32_t dst, const void* src) {
    asm volatile("cp.async.cg.shared.global [%0], [%1], 16;" :: "r"(dst), "l"(src) : "memory");
}
#define CP_COMMIT() asm volatile("cp.async.commit_group;" ::: "memory")
#define CP_WAIT1()  asm volatile("cp.async.wait_group 1;" ::: "memory")

__device__ __forceinline__ void mma_tf32(float (&d)[4], const uint32_t (&a)[4],
                                         const uint32_t (&b)[2]) {
    asm volatile(
        "mma.sync.aligned.m16n8k8.row.col.f32.tf32.tf32.f32 "
        "{%0,%1,%2,%3}, {%4,%5,%6,%7}, {%8,%9}, {%0,%1,%2,%3};"
        : "+f"(d[0]), "+f"(d[1]), "+f"(d[2]), "+f"(d[3])
        : "r"(a[0]), "r"(a[1]), "r"(a[2]), "r"(a[3]), "r"(b[0]), "r"(b[1]));
}
__device__ __forceinline__ uint32_t to_tf32(float x) {
    uint32_t r;
    asm("cvt.rna.tf32.f32 %0, %1;" : "=r"(r) : "f"(x));
    return r;
}

// ---------------------------------------------------------------------------
// prep: pack [actor_w | critic_w | 0...] into mma B-fragment order (tf32).
// entry e: lane=e&31, G=(e>>5)%9, ks=(e>>5)/9 ; nloc=lane>>2, k=ks*8+(lane&3)
// ---------------------------------------------------------------------------
__global__ void kprep(const float* __restrict__ aw, const float* __restrict__ cw) {
    int e = blockIdx.x * 256 + threadIdx.x;      // 18432 entries
    int lane = e & 31, gk = e >> 5;
    int G = gk % NGRP, ks = gk / NGRP;
    int nloc = lane >> 2;
    int k = ks * 8 + (lane & 3);
    float w0, w1;
    if (G < 8) {
        int n = G * 8 + nloc;
        w0 = aw[k * A_DIM + n];
        w1 = aw[(k + 4) * A_DIM + n];
    } else {
        w0 = (nloc == 0) ? cw[k] : 0.f;
        w1 = (nloc == 0) ? cw[k + 4] : 0.f;
    }
    float2 v;
    v.x = __uint_as_float(to_tf32(w0));
    v.y = __uint_as_float(to_tf32(w1));
    g_wfrag[e] = v;
}

// ---------------------------------------------------------------------------
// slab loader: stage s%3 <- states & next_states rows [row0,row0+128),
// cols [32s, 32s+32). 2048 granules of 16B, 256 threads x 8.
// ---------------------------------------------------------------------------
__device__ __forceinline__ void issue_slab(uint32_t su, int s,
                                           const float* __restrict__ states,
                                           const float* __restrict__ next_states,
                                           int row0, int tid) {
    const uint32_t sbase = su + OFF_RING + (s % RING) * STAGE_BYTES;
    const size_t goff = (size_t)row0 * S_DIM + s * 32;
#pragma unroll
    for (int i = 0; i < 8; ++i) {
        int g = tid + i * 256;                 // 0..2047
        int mtx = g >> 10;                     // 0: states, 1: next_states
        int r = (g & 1023) >> 3, u = g & 7;
        const float* src = (mtx ? next_states : states) + goff + (size_t)r * S_DIM + u * 4;
        cpa16(sbase + mtx * SLAB_BYTES + r * 144 + u * 16, src);
    }
}

// ---------------------------------------------------------------------------
// Main fused kernel
// ---------------------------------------------------------------------------
__global__ void __launch_bounds__(256, 2)
k1_mma(const float* __restrict__ states,
       const float* __restrict__ next_states,
       const float* __restrict__ rewards,
       const int*   __restrict__ dones,
       const int*   __restrict__ actions,
       const float* __restrict__ log_probs,
       const float* __restrict__ actor_b,
       const float* __restrict__ critic_b) {
    extern __shared__ __align__(16) char smem[];
    const uint32_t su = smem_to_u32(smem);
    const int tid  = threadIdx.x;
    const int wid  = tid >> 5;
    const int lane = tid & 31;
    const int q = lane >> 2, j = lane & 3;
    const int wm = wid >> 1, wn = wid & 1;
    const int row0 = blockIdx.x * BM;

    float* sv   = (float*)(smem + OFF_SV);
    float* snv  = (float*)(smem + OFF_SNV);
    float* sEnt = (float*)(smem + OFF_ENT);
    const float cb = critic_b[0];

    // bias for this thread's actor columns
    float bcol[8];
#pragma unroll
    for (int g = 0; g < 4; ++g) {
        const int c = wn * 32 + g * 8 + j * 2;
        bcol[2 * g]     = __ldg(actor_b + c);
        bcol[2 * g + 1] = __ldg(actor_b + c + 1);
    }

    // prefetch 2 stages
    issue_slab(su, 0, states, next_states, row0, tid); CP_COMMIT();
    issue_slab(su, 1, states, next_states, row0, tid); CP_COMMIT();

    float acc[2][4][4];     // actor: [mtile][ngroup][frag]
    float accC[2][4];       // critic column group
#pragma unroll
    for (int mt = 0; mt < 2; ++mt) {
#pragma unroll
        for (int g = 0; g < 4; ++g)
#pragma unroll
            for (int p = 0; p < 4; ++p) acc[mt][g][p] = 0.f;
#pragma unroll
        for (int p = 0; p < 4; ++p) accC[mt][p] = 0.f;
    }

    const float2* wf = (const float2*)g_wfrag;

    for (int s = 0; s < SLABS; ++s) {
        CP_WAIT1();
        __syncthreads();
        if (s + 2 < SLABS) issue_slab(su, s + 2, states, next_states, row0, tid);
        CP_COMMIT();

        const char* stage = smem + OFF_RING + (size_t)(s % RING) * STAGE_BYTES;
        const float* As = (const float*)stage;
        const float* Ns = (const float*)(stage + SLAB_BYTES);
        const float* Ar = As + (wm * 32 + q) * A_ROW_F + j;
        const float* Nr = Ns + (wm * 32 + q) * A_ROW_F + j;

#pragma unroll
        for (int ks = 0; ks < 4; ++ks) {
            const int kidx = (s * 4 + ks) * NGRP;
            uint32_t bf[4][2], bfc[2];
#pragma unroll
            for (int g = 0; g < 4; ++g) {
                float2 v = __ldg(&wf[(kidx + wn * 4 + g) * 32 + lane]);
                bf[g][0] = __float_as_uint(v.x);
                bf[g][1] = __float_as_uint(v.y);
            }
            {
                float2 v = __ldg(&wf[(kidx + 8) * 32 + lane]);
                bfc[0] = __float_as_uint(v.x);
                bfc[1] = __float_as_uint(v.y);
            }
#pragma unroll
            for (int mt = 0; mt < 2; ++mt) {
                uint32_t af[4];
                const float* Am = Ar + mt * 16 * A_ROW_F + ks * 8;
                af[0] = __float_as_uint(Am[0]);
                af[1] = __float_as_uint(Am[8 * A_ROW_F]);
                af[2] = __float_as_uint(Am[4]);
                af[3] = __float_as_uint(Am[8 * A_ROW_F + 4]);
#pragma unroll
                for (int g = 0; g < 4; ++g) mma_tf32(acc[mt][g], af, bf[g]);
                if (wn) {
                    mma_tf32(accC[mt], af, bfc);      // values from states
                } else {
                    uint32_t an[4];
                    const float* Nm = Nr + mt * 16 * A_ROW_F + ks * 8;
                    an[0] = __float_as_uint(Nm[0]);
                    an[1] = __float_as_uint(Nm[8 * A_ROW_F]);
                    an[2] = __float_as_uint(Nm[4]);
                    an[3] = __float_as_uint(Nm[8 * A_ROW_F + 4]);
                    mma_tf32(accC[mt], an, bfc);      // next_values
                }
            }
        }
    }
    __syncthreads();   // all LDS reads of the ring done; safe to reuse as slog

    // values / next_values: critic column (group 8, local col 0 -> j==0 threads)
    if (j == 0) {
#pragma unroll
        for (int mt = 0; mt < 2; ++mt) {
            const int r = wm * 32 + mt * 16 + q;
            float* dst = wn ? sv : snv;
            dst[r]     = accC[mt][0] + cb;
            dst[r + 8] = accC[mt][2] + cb;
        }
    }

    // dump logits (+bias) into smem (ring reuse)
    float* slog = (float*)(smem + OFF_RING);
#pragma unroll
    for (int mt = 0; mt < 2; ++mt) {
        const int r = wm * 32 + mt * 16 + q;
#pragma unroll
        for (int g = 0; g < 4; ++g) {
            const int c = wn * 32 + g * 8 + j * 2;
            float2 lo = make_float2(acc[mt][g][0] + bcol[2 * g], acc[mt][g][1] + bcol[2 * g + 1]);
            float2 hi = make_float2(acc[mt][g][2] + bcol[2 * g], acc[mt][g][3] + bcol[2 * g + 1]);
            *(float2*)&slog[r * LOG_STRIDE + c] = lo;
            *(float2*)&slog[(r + 8) * LOG_STRIDE + c] = hi;
        }
    }
    __syncthreads();

    // softmax / ratio / delta / entropy: warps 0..3, one row per lane
    if (wid < 4) {
        const int r = wid * 32 + lane;
        const int grow = row0 + r;
        const float* lr = &slog[r * LOG_STRIDE];
        float m = -1e30f;
#pragma unroll
        for (int c = 0; c < A_DIM; ++c) m = fmaxf(m, lr[c]);
        const int a = actions[grow];
        float se = 0.f, pe = 0.f;
#pragma unroll
        for (int c = 0; c < A_DIM; ++c) {
            float t = lr[c] - m;
            float e = __expf(t);
            se += e;
            pe = fmaf(e, t, pe);
        }
        const float la = lr[a] - m;
        const float logse = __logf(se);
        const float ratio = __expf(la - logse - log_probs[grow]);
        const float nd = 1.f - (float)dones[grow];
        g_delta[grow] = rewards[grow] + GAMMA_F * snv[r] * nd - sv[r];
        g_ratio[grow] = ratio;
        float ent = logse - pe / se;
#pragma unroll
        for (int o = 16; o > 0; o >>= 1) ent += __shfl_xor_sync(0xffffffffu, ent, o);
        if (lane == 0) sEnt[wid] = ent;
    }
    __syncthreads();
    if (tid == 0) g_ent[blockIdx.x] = sEnt[0] + sEnt[1] + sEnt[2] + sEnt[3];
}

// ---------------------------------------------------------------------------
// GAE scan
// ---------------------------------------------------------------------------
__device__ __forceinline__ void thread_affine(const int* __restrict__ dones,
                                              int base, float (&d)[8], float (&c)[8],
                                              float& A, float& Bv) {
    float4 d0 = *(const float4*)&g_delta[base];
    float4 d1 = *(const float4*)&g_delta[base + 4];
    int4 q0 = *(const int4*)&dones[base];
    int4 q1 = *(const int4*)&dones[base + 4];
    d[0]=d0.x; d[1]=d0.y; d[2]=d0.z; d[3]=d0.w;
    d[4]=d1.x; d[5]=d1.y; d[6]=d1.z; d[7]=d1.w;
    c[0]=GL_F*(1.f-(float)q0.x); c[1]=GL_F*(1.f-(float)q0.y);
    c[2]=GL_F*(1.f-(float)q0.z); c[3]=GL_F*(1.f-(float)q0.w);
    c[4]=GL_F*(1.f-(float)q1.x); c[5]=GL_F*(1.f-(float)q1.y);
    c[6]=GL_F*(1.f-(float)q1.z); c[7]=GL_F*(1.f-(float)q1.w);
    A = 1.f; Bv = 0.f;
#pragma unroll
    for (int jj = 7; jj >= 0; --jj) { Bv = fmaf(c[jj], Bv, d[jj]); A = c[jj] * A; }
}

__global__ void __launch_bounds__(256)
k2_chunk_reduce(const int* __restrict__ dones) {
    __shared__ float sa[256], sb[256];
    const int tid = threadIdx.x;
    const int base = blockIdx.x * CHUNK + tid * 8;
    float d[8], c[8], A, Bv;
    thread_affine(dones, base, d, c, A, Bv);
    sa[tid] = A; sb[tid] = Bv;
    __syncthreads();
    for (int s = 1; s < 256; s <<= 1) {
        if ((tid & (2 * s - 1)) == 0) {
            float al = sa[tid], bl = sb[tid];
            float ar = sa[tid + s], br = sb[tid + s];
            sa[tid] = al * ar;
            sb[tid] = fmaf(al, br, bl);
        }
        __syncthreads();
    }
    if (tid == 0) { g_cA[blockIdx.x] = sa[0]; g_cB[blockIdx.x] = sb[0]; }
}

// k4: fused chunk-boundary computation (suffix scan over 128 composites)
// + per-chunk application + partial reductions.
__global__ void __launch_bounds__(256)
k4_apply(const int* __restrict__ dones, int nb) {
    __shared__ float sa[256], sb[256];
    __shared__ float ca[NB_MAX], cbv[NB_MAX];
    const int tid = threadIdx.x;

    // load all chunk composites, suffix-scan them (inclusive)
    if (tid < NB_MAX) { ca[tid] = g_cA[tid]; cbv[tid] = g_cB[tid]; }
    __syncthreads();
    for (int dd = 1; dd < NB_MAX; dd <<= 1) {
        float a = 0.f, b = 0.f, ar = 1.f, br = 0.f;
        if (tid < NB_MAX) {
            a = ca[tid]; b = cbv[tid];
            if (tid + dd < NB_MAX) { ar = ca[tid + dd]; br = cbv[tid + dd]; }
        }
        __syncthreads();
        if (tid < NB_MAX) { ca[tid] = a * ar; cbv[tid] = fmaf(a, br, b); }
        __syncthreads();
    }
    const int blk = blockIdx.x;
    const float xb = (blk + 1 < nb) ? cbv[blk + 1] : 0.f;   // adv entering chunk

    const int base = blk * CHUNK + tid * 8;
    float d[8], c[8], A, Bv;
    thread_affine(dones, base, d, c, A, Bv);
    sa[tid] = A; sb[tid] = Bv;
    __syncthreads();
    for (int dd = 1; dd < 256; dd <<= 1) {
        float al = sa[tid], bl = sb[tid];
        float ar = 1.f, br = 0.f;
        if (tid + dd < 256) { ar = sa[tid + dd]; br = sb[tid + dd]; }
        __syncthreads();
        sa[tid] = al * ar;
        sb[tid] = fmaf(al, br, bl);
        __syncthreads();
    }
    float xin = (tid == 255) ? xb : fmaf(sa[tid + 1], xb, sb[tid + 1]);

    float4 r0 = *(const float4*)&g_ratio[base];
    float4 r1 = *(const float4*)&g_ratio[base + 4];
    float rt[8] = {r0.x, r0.y, r0.z, r0.w, r1.x, r1.y, r1.z, r1.w};

    float adv = xin, s1 = 0.f, s2 = 0.f;
#pragma unroll
    for (int jj = 7; jj >= 0; --jj) {
        adv = fmaf(c[jj], adv, d[jj]);
        const float r = rt[jj];
        const float rc = fminf(fmaxf(r, CLIP_LO), CLIP_HI);
        s1 += fminf(r * adv, rc * adv);
        s2 = fmaf(adv, adv, s2);
    }
    __syncthreads();
    sa[tid] = s1; sb[tid] = s2;
    __syncthreads();
    for (int s = 128; s > 0; s >>= 1) {
        if (tid < s) { sa[tid] += sa[tid + s]; sb[tid] += sb[tid + s]; }
        __syncthreads();
    }
    if (tid == 0) { g_surr[blk] = sa[0]; g_adv2[blk] = sb[0]; }
}

__global__ void __launch_bounds__(256)
k5_final(float* __restrict__ out, int T, int nb, int nb1) {
    __shared__ float se_[256], ss_[256], sv_[256];
    const int tid = threadIdx.x;
    float e = 0.f, s = 0.f, v = 0.f;
    for (int i = tid; i < nb1; i += 256) e += g_ent[i];
    for (int i = tid; i < nb; i += 256) { s += g_surr[i]; v += g_adv2[i]; }
    se_[tid] = e; ss_[tid] = s; sv_[tid] = v;
    __syncthreads();
    for (int st = 128; st > 0; st >>= 1) {
        if (tid < st) {
            se_[tid] += se_[tid + st];
            ss_[tid] += ss_[tid + st];
            sv_[tid] += sv_[tid + st];
        }
        __syncthreads();
    }
    if (tid == 0) {
        const float invT = 1.f / (float)T;
        out[0] = -(ss_[0] * invT) - ENT_C * (se_[0] * invT);
        out[1] = sv_[0] * invT;
    }
}

extern "C" void kernel_launch(void* const* d_in, const int* in_sizes, int n_in,
                              void* d_out, int out_size) {
    const float* states      = (const float*)d_in[0];
    const float* next_states = (const float*)d_in[1];
    const float* rewards     = (const float*)d_in[2];
    const int*   dones       = (const int*)  d_in[3];
    const int*   actions     = (const int*)  d_in[4];
    const float* log_probs   = (const float*)d_in[5];
    const float* actor_w     = (const float*)d_in[6];
    const float* actor_b     = (const float*)d_in[7];
    const float* critic_w    = (const float*)d_in[8];
    const float* critic_b    = (const float*)d_in[9];
    float* out = (float*)d_out;

    const int T   = in_sizes[2];
    const int nb1 = T / BM;       // 2048
    const int nb  = T / CHUNK;    // 128

    cudaFuncSetAttribute(k1_mma, cudaFuncAttributeMaxDynamicSharedMemorySize, SMEM_TOTAL);

    kprep<<<(64 * NGRP * 32) / 256, 256>>>(actor_w, critic_w);
    k1_mma<<<nb1, 256, SMEM_TOTAL>>>(states, next_states, rewards, dones, actions,
                                     log_probs, actor_b, critic_b);
    k2_chunk_reduce<<<nb, 256>>>(dones);
    k4_apply<<<nb, 256>>>(dones, nb);
    k5_final<<<1, 256>>>(out, T, nb, nb1);
}

// round 5
// speedup vs baseline: 1.5106x; 1.0115x over previous
#include <cuda_runtime.h>
#include <math.h>
#include <stdint.h>

// ---------------------------------------------------------------------------
// PPO fused loss on GB300 — persistent-CTA mma.sync tf32 GEMM (actor + critic),
// register-resident epilogue, continuous cp.async ring, blocked-scan GAE.
// ---------------------------------------------------------------------------

#define T_MAX   262144
#define S_DIM   512
#define A_DIM   64
#define BM      128
#define GAMMA_F 0.99f
#define GL_F    (0.99f * 0.98f)
#define CLIP_LO 0.8f
#define CLIP_HI 1.2f
#define ENT_C   0.01f
#define CHUNK   2048
#define NB_MAX  (T_MAX / CHUNK)
#define NGRP    9                          // 8 actor col-groups + 1 critic group
#define GRID1   304                        // 2 CTAs x 152 SMs

// scratch
__device__ float g_delta[T_MAX];
__device__ float g_ratio[T_MAX];
__device__ float g_ent[T_MAX / BM];
__device__ float g_cA[NB_MAX];
__device__ float g_cB[NB_MAX];
__device__ float g_surr[NB_MAX];
__device__ float g_adv2[NB_MAX];
// B fragments: [64 ksteps][9 groups][32 lanes] float2 (tf32-rounded)
__device__ __align__(16) float2 g_wfrag[64 * NGRP * 32];

// ---------------- smem layout ----------------
#define SLABS        16
#define RING         3
#define A_ROW_F      36                     // 32 floats + 4 pad (144 B rows)
#define SLAB_BYTES   (128 * 144)            // 18432
#define STAGE_BYTES  (2 * SLAB_BYTES)       // states + next_states = 36864
#define OFF_ENT   (RING * STAGE_BYTES)      // 110592
#define SMEM_TOTAL (OFF_ENT + 64)           // 110656

// ---------------- PTX helpers ----------------
__device__ __forceinline__ uint32_t smem_to_u32(const void* p) {
    uint32_t a;
    asm("{ .reg .u64 t; cvta.to.shared.u64 t, %1; cvt.u32.u64 %0, t; }" : "=r"(a) : "l"(p));
    return a;
}
__device__ __forceinline__ void cpa16(uint32_t dst, const void* src) {
    asm volatile("cp.async.cg.shared.global [%0], [%1], 16;" :: "r"(dst), "l"(src) : "memory");
}
#define CP_COMMIT() asm volatile("cp.async.commit_group;" ::: "memory")
#define CP_WAIT1()  asm volatile("cp.async.wait_group 1;" ::: "memory")
#define CP_WAIT0()  asm volatile("cp.async.wait_group 0;" ::: "memory")

__device__ __forceinline__ void mma_tf32(float (&d)[4], const uint32_t (&a)[4],
                                         const uint32_t (&b)[2]) {
    asm volatile(
        "mma.sync.aligned.m16n8k8.row.col.f32.tf32.tf32.f32 "
        "{%0,%1,%2,%3}, {%4,%5,%6,%7}, {%8,%9}, {%0,%1,%2,%3};"
        : "+f"(d[0]), "+f"(d[1]), "+f"(d[2]), "+f"(d[3])
        : "r"(a[0]), "r"(a[1]), "r"(a[2]), "r"(a[3]), "r"(b[0]), "r"(b[1]));
}
__device__ __forceinline__ uint32_t to_tf32(float x) {
    uint32_t r;
    asm("cvt.rna.tf32.f32 %0, %1;" : "=r"(r) : "f"(x));
    return r;
}

// ---------------------------------------------------------------------------
// prep: pack [actor_w | critic_w] into mma B-fragment order (tf32-rounded).
// ---------------------------------------------------------------------------
__global__ void kprep(const float* __restrict__ aw, const float* __restrict__ cw) {
    int e = blockIdx.x * 256 + threadIdx.x;      // 18432 entries
    int lane = e & 31, gk = e >> 5;
    int G = gk % NGRP, ks = gk / NGRP;
    int nloc = lane >> 2;
    int k = ks * 8 + (lane & 3);
    float w0, w1;
    if (G < 8) {
        int n = G * 8 + nloc;
        w0 = aw[k * A_DIM + n];
        w1 = aw[(k + 4) * A_DIM + n];
    } else {
        w0 = (nloc == 0) ? cw[k] : 0.f;
        w1 = (nloc == 0) ? cw[k + 4] : 0.f;
    }
    float2 v;
    v.x = __uint_as_float(to_tf32(w0));
    v.y = __uint_as_float(to_tf32(w1));
    g_wfrag[e] = v;
}

// ---------------------------------------------------------------------------
// linear slab loader: L -> (tile, s). tile = bid + (L>>4)*gdim. Skips invalid.
// ---------------------------------------------------------------------------
__device__ __forceinline__ void issue_slab(uint32_t su, int L,
                                           const float* __restrict__ states,
                                           const float* __restrict__ next_states,
                                           int bid, int gdim, int nb1, int tid) {
    const int tile = bid + (L >> 4) * gdim;
    if (tile >= nb1) return;
    const int s = L & 15;
    const uint32_t sbase = su + (L % RING) * STAGE_BYTES;
    const size_t goff = (size_t)tile * BM * S_DIM + s * 32;
#pragma unroll
    for (int i = 0; i < 8; ++i) {
        int g = tid + i * 256;                 // 0..2047
        int mtx = g >> 10;                     // 0: states, 1: next_states
        int r = (g & 1023) >> 3, u = g & 7;
        const float* src = (mtx ? next_states : states) + goff + (size_t)r * S_DIM + u * 4;
        cpa16(sbase + mtx * SLAB_BYTES + r * 144 + u * 16, src);
    }
}

// ---------------------------------------------------------------------------
// Main fused kernel (persistent)
// ---------------------------------------------------------------------------
__global__ void __launch_bounds__(256, 2)
k1_mma(const float* __restrict__ states,
       const float* __restrict__ next_states,
       const float* __restrict__ rewards,
       const int*   __restrict__ dones,
       const int*   __restrict__ actions,
       const float* __restrict__ log_probs,
       const float* __restrict__ actor_b,
       const float* __restrict__ critic_b,
       int nb1) {
    extern __shared__ __align__(16) char smem[];
    const uint32_t su = smem_to_u32(smem);
    const int tid  = threadIdx.x;
    const int w    = tid >> 5;                 // warp 0..7 -> rows 16w..16w+15
    const int lane = tid & 31;
    const int q = lane >> 2, j = lane & 3;
    const int bid = blockIdx.x, gdim = gridDim.x;

    float* sEnt = (float*)(smem + OFF_ENT);
    const float cb = critic_b[0];

    // bias for this thread's 16 actor columns: col = g*8 + j*2 + b
    float2 bias[8];
#pragma unroll
    for (int g = 0; g < 8; ++g)
        bias[g] = __ldg((const float2*)(actor_b + g * 8 + j * 2));

    // prologue: prefetch 2 stages
    issue_slab(su, 0, states, next_states, bid, gdim, nb1, tid); CP_COMMIT();
    issue_slab(su, 1, states, next_states, bid, gdim, nb1, tid); CP_COMMIT();

    const float2* wf = (const float2*)g_wfrag;

    for (int it = 0;; ++it) {
        const int tile = bid + it * gdim;
        if (tile >= nb1) break;
        const int row0 = tile * BM;

        float acc[8][4];     // actor groups
        float accV[4], accN[4];
#pragma unroll
        for (int g = 0; g < 8; ++g)
#pragma unroll
            for (int p = 0; p < 4; ++p) acc[g][p] = 0.f;
#pragma unroll
        for (int p = 0; p < 4; ++p) { accV[p] = 0.f; accN[p] = 0.f; }

        for (int s = 0; s < SLABS; ++s) {
            const int L = it * SLABS + s;
            CP_WAIT1();
            __syncthreads();
            issue_slab(su, L + 2, states, next_states, bid, gdim, nb1, tid);
            CP_COMMIT();

            const char* stage = smem + (size_t)(L % RING) * STAGE_BYTES;
            const float* Ar = (const float*)stage + (16 * w + q) * A_ROW_F + j;
            const float* Nr = (const float*)(stage + SLAB_BYTES) + (16 * w + q) * A_ROW_F + j;

#pragma unroll
            for (int ks = 0; ks < 4; ++ks) {
                uint32_t af[4], an[4];
                const float* Am = Ar + ks * 8;
                af[0] = __float_as_uint(Am[0]);
                af[1] = __float_as_uint(Am[8 * A_ROW_F]);
                af[2] = __float_as_uint(Am[4]);
                af[3] = __float_as_uint(Am[8 * A_ROW_F + 4]);
                const float* Nm = Nr + ks * 8;
                an[0] = __float_as_uint(Nm[0]);
                an[1] = __float_as_uint(Nm[8 * A_ROW_F]);
                an[2] = __float_as_uint(Nm[4]);
                an[3] = __float_as_uint(Nm[8 * A_ROW_F + 4]);

                const int kidx = (s * 4 + ks) * NGRP;
                uint32_t bfc[2];
                {
                    float2 v = __ldg(&wf[(kidx + 8) * 32 + lane]);
                    bfc[0] = __float_as_uint(v.x);
                    bfc[1] = __float_as_uint(v.y);
                }
#pragma unroll
                for (int g = 0; g < 8; ++g) {
                    uint32_t bf[2];
                    float2 v = __ldg(&wf[(kidx + g) * 32 + lane]);
                    bf[0] = __float_as_uint(v.x);
                    bf[1] = __float_as_uint(v.y);
                    mma_tf32(acc[g], af, bf);
                }
                mma_tf32(accV, af, bfc);   // values
                mma_tf32(accN, an, bfc);   // next_values
            }
        }

        // ---- register epilogue: rows 16w+q (half 0) and 16w+q+8 (half 1) ----
        float ent2 = 0.f;
#pragma unroll
        for (int half = 0; half < 2; ++half) {
            float tl[8][2];
            float m = -1e30f;
#pragma unroll
            for (int g = 0; g < 8; ++g) {
                tl[g][0] = acc[g][half * 2]     + bias[g].x;
                tl[g][1] = acc[g][half * 2 + 1] + bias[g].y;
                m = fmaxf(m, fmaxf(tl[g][0], tl[g][1]));
            }
            m = fmaxf(m, __shfl_xor_sync(0xffffffffu, m, 1));
            m = fmaxf(m, __shfl_xor_sync(0xffffffffu, m, 2));

            float se = 0.f, pe = 0.f;
#pragma unroll
            for (int g = 0; g < 8; ++g) {
#pragma unroll
                for (int b = 0; b < 2; ++b) {
                    float t = tl[g][b] - m;
                    tl[g][b] = t;
                    float e = __expf(t);
                    se += e;
                    pe = fmaf(e, t, pe);
                }
            }
            se += __shfl_xor_sync(0xffffffffu, se, 1);
            se += __shfl_xor_sync(0xffffffffu, se, 2);
            pe += __shfl_xor_sync(0xffffffffu, pe, 1);
            pe += __shfl_xor_sync(0xffffffffu, pe, 2);

            const int r = 16 * w + q + half * 8;
            const int grow = row0 + r;
            const int a = __ldg(actions + grow);
            float cand = -1e30f;
            if (j == ((a >> 1) & 3)) {
                const int ga = a >> 3, ba = a & 1;
#pragma unroll
                for (int g = 0; g < 8; ++g)
                    if (g == ga) cand = ba ? tl[g][1] : tl[g][0];
            }
            cand = fmaxf(cand, __shfl_xor_sync(0xffffffffu, cand, 1));
            cand = fmaxf(cand, __shfl_xor_sync(0xffffffffu, cand, 2));

            if (j == 0) {
                const float logse = __logf(se);
                const float ratio = __expf(cand - logse - __ldg(log_probs + grow));
                const float nd = 1.f - (float)__ldg(dones + grow);
                const float v  = accV[half * 2] + cb;
                const float nv = accN[half * 2] + cb;
                g_delta[grow] = __ldg(rewards + grow) + GAMMA_F * nv * nd - v;
                g_ratio[grow] = ratio;
                ent2 += logse - pe / se;
            }
        }
        // warp entropy sum (only j==0 lanes hold nonzero ent2)
#pragma unroll
        for (int o = 16; o > 0; o >>= 1) ent2 += __shfl_xor_sync(0xffffffffu, ent2, o);
        if (lane == 0) sEnt[w] = ent2;
        __syncthreads();
        if (tid == 0) {
            float s8 = 0.f;
#pragma unroll
            for (int i = 0; i < 8; ++i) s8 += sEnt[i];
            g_ent[tile] = s8;
        }
    }
    CP_WAIT0();   // retire dangling prefetch groups before exit
}

// ---------------------------------------------------------------------------
// GAE scan
// ---------------------------------------------------------------------------
__device__ __forceinline__ void thread_affine(const int* __restrict__ dones,
                                              int base, float (&d)[8], float (&c)[8],
                                              float& A, float& Bv) {
    float4 d0 = *(const float4*)&g_delta[base];
    float4 d1 = *(const float4*)&g_delta[base + 4];
    int4 q0 = *(const int4*)&dones[base];
    int4 q1 = *(const int4*)&dones[base + 4];
    d[0]=d0.x; d[1]=d0.y; d[2]=d0.z; d[3]=d0.w;
    d[4]=d1.x; d[5]=d1.y; d[6]=d1.z; d[7]=d1.w;
    c[0]=GL_F*(1.f-(float)q0.x); c[1]=GL_F*(1.f-(float)q0.y);
    c[2]=GL_F*(1.f-(float)q0.z); c[3]=GL_F*(1.f-(float)q0.w);
    c[4]=GL_F*(1.f-(float)q1.x); c[5]=GL_F*(1.f-(float)q1.y);
    c[6]=GL_F*(1.f-(float)q1.z); c[7]=GL_F*(1.f-(float)q1.w);
    A = 1.f; Bv = 0.f;
#pragma unroll
    for (int jj = 7; jj >= 0; --jj) { Bv = fmaf(c[jj], Bv, d[jj]); A = c[jj] * A; }
}

__global__ void __launch_bounds__(256)
k2_chunk_reduce(const int* __restrict__ dones) {
    __shared__ float sa[256], sb[256];
    const int tid = threadIdx.x;
    const int base = blockIdx.x * CHUNK + tid * 8;
    float d[8], c[8], A, Bv;
    thread_affine(dones, base, d, c, A, Bv);
    sa[tid] = A; sb[tid] = Bv;
    __syncthreads();
    for (int s = 1; s < 256; s <<= 1) {
        if ((tid & (2 * s - 1)) == 0) {
            float al = sa[tid], bl = sb[tid];
            float ar = sa[tid + s], br = sb[tid + s];
            sa[tid] = al * ar;
            sb[tid] = fmaf(al, br, bl);
        }
        __syncthreads();
    }
    if (tid == 0) { g_cA[blockIdx.x] = sa[0]; g_cB[blockIdx.x] = sb[0]; }
}

// fused chunk-boundary suffix scan + application + partial reductions
__global__ void __launch_bounds__(256)
k4_apply(const int* __restrict__ dones, int nb) {
    __shared__ float sa[256], sb[256];
    __shared__ float ca[NB_MAX], cbv[NB_MAX];
    const int tid = threadIdx.x;

    if (tid < NB_MAX) { ca[tid] = g_cA[tid]; cbv[tid] = g_cB[tid]; }
    __syncthreads();
    for (int dd = 1; dd < NB_MAX; dd <<= 1) {
        float a = 0.f, b = 0.f, ar = 1.f, br = 0.f;
        if (tid < NB_MAX) {
            a = ca[tid]; b = cbv[tid];
            if (tid + dd < NB_MAX) { ar = ca[tid + dd]; br = cbv[tid + dd]; }
        }
        __syncthreads();
        if (tid < NB_MAX) { ca[tid] = a * ar; cbv[tid] = fmaf(a, br, b); }
        __syncthreads();
    }
    const int blk = blockIdx.x;
    const float xb = (blk + 1 < nb) ? cbv[blk + 1] : 0.f;

    const int base = blk * CHUNK + tid * 8;
    float d[8], c[8], A, Bv;
    thread_affine(dones, base, d, c, A, Bv);
    sa[tid] = A; sb[tid] = Bv;
    __syncthreads();
    for (int dd = 1; dd < 256; dd <<= 1) {
        float al = sa[tid], bl = sb[tid];
        float ar = 1.f, br = 0.f;
        if (tid + dd < 256) { ar = sa[tid + dd]; br = sb[tid + dd]; }
        __syncthreads();
        sa[tid] = al * ar;
        sb[tid] = fmaf(al, br, bl);
        __syncthreads();
    }
    float xin = (tid == 255) ? xb : fmaf(sa[tid + 1], xb, sb[tid + 1]);

    float4 r0 = *(const float4*)&g_ratio[base];
    float4 r1 = *(const float4*)&g_ratio[base + 4];
    float rt[8] = {r0.x, r0.y, r0.z, r0.w, r1.x, r1.y, r1.z, r1.w};

    float adv = xin, s1 = 0.f, s2 = 0.f;
#pragma unroll
    for (int jj = 7; jj >= 0; --jj) {
        adv = fmaf(c[jj], adv, d[jj]);
        const float r = rt[jj];
        const float rc = fminf(fmaxf(r, CLIP_LO), CLIP_HI);
        s1 += fminf(r * adv, rc * adv);
        s2 = fmaf(adv, adv, s2);
    }
    __syncthreads();
    sa[tid] = s1; sb[tid] = s2;
    __syncthreads();
    for (int s = 128; s > 0; s >>= 1) {
        if (tid < s) { sa[tid] += sa[tid + s]; sb[tid] += sb[tid + s]; }
        __syncthreads();
    }
    if (tid == 0) { g_surr[blk] = sa[0]; g_adv2[blk] = sb[0]; }
}

__global__ void __launch_bounds__(256)
k5_final(float* __restrict__ out, int T, int nb, int nb1) {
    __shared__ float se_[256], ss_[256], sv_[256];
    const int tid = threadIdx.x;
    float e = 0.f, s = 0.f, v = 0.f;
    for (int i = tid; i < nb1; i += 256) e += g_ent[i];
    for (int i = tid; i < nb; i += 256) { s += g_surr[i]; v += g_adv2[i]; }
    se_[tid] = e; ss_[tid] = s; sv_[tid] = v;
    __syncthreads();
    for (int st = 128; st > 0; st >>= 1) {
        if (tid < st) {
            se_[tid] += se_[tid + st];
            ss_[tid] += ss_[tid + st];
            sv_[tid] += sv_[tid + st];
        }
        __syncthreads();
    }
    if (tid == 0) {
        const float invT = 1.f / (float)T;
        out[0] = -(ss_[0] * invT) - ENT_C * (se_[0] * invT);
        out[1] = sv_[0] * invT;
    }
}

extern "C" void kernel_launch(void* const* d_in, const int* in_sizes, int n_in,
                              void* d_out, int out_size) {
    const float* states      = (const float*)d_in[0];
    const float* next_states = (const float*)d_in[1];
    const float* rewards     = (const float*)d_in[2];
    const int*   dones       = (const int*)  d_in[3];
    const int*   actions     = (const int*)  d_in[4];
    const float* log_probs   = (const float*)d_in[5];
    const float* actor_w     = (const float*)d_in[6];
    const float* actor_b     = (const float*)d_in[7];
    const float* critic_w    = (const float*)d_in[8];
    const float* critic_b    = (const float*)d_in[9];
    float* out = (float*)d_out;

    const int T   = in_sizes[2];
    const int nb1 = T / BM;       // 2048
    const int nb  = T / CHUNK;    // 128
    const int grid1 = nb1 < GRID1 ? nb1 : GRID1;

    cudaFuncSetAttribute(k1_mma, cudaFuncAttributeMaxDynamicSharedMemorySize, SMEM_TOTAL);

    kprep<<<(64 * NGRP * 32) / 256, 256>>>(actor_w, critic_w);
    k1_mma<<<grid1, 256, SMEM_TOTAL>>>(states, next_states, rewards, dones, actions,
                                       log_probs, actor_b, critic_b, nb1);
    k2_chunk_reduce<<<nb, 256>>>(dones);
    k4_apply<<<nb, 256>>>(dones, nb);
    k5_final<<<1, 256>>>(out, T, nb, nb1);
}

// round 6
// speedup vs baseline: 1.9939x; 1.3200x over previous
#include <cuda_runtime.h>
#include <math.h>
#include <stdint.h>

// ---------------------------------------------------------------------------
// PPO fused loss on GB300 — persistent mma.sync tf32 GEMM (actor + critic),
// B fragments staged per-slab through the cp.async stream (LDS, not L2-LDG),
// register-resident epilogue, blocked-scan GAE.
// ---------------------------------------------------------------------------

#define T_MAX   262144
#define S_DIM   512
#define A_DIM   64
#define BM      128
#define GAMMA_F 0.99f
#define GL_F    (0.99f * 0.98f)
#define CLIP_LO 0.8f
#define CLIP_HI 1.2f
#define ENT_C   0.01f
#define CHUNK   2048
#define NB_MAX  (T_MAX / CHUNK)
#define NGRP    9                          // 8 actor col-groups + 1 critic group
#define GRID1   304                        // 2 CTAs x 152 SMs

// scratch
__device__ float g_delta[T_MAX];
__device__ float g_ratio[T_MAX];
__device__ float g_ent[T_MAX / BM];
__device__ float g_cA[NB_MAX];
__device__ float g_cB[NB_MAX];
__device__ float g_surr[NB_MAX];
__device__ float g_adv2[NB_MAX];
// B fragments: [64 ksteps][9 groups][32 lanes] float2 (tf32-rounded)
__device__ __align__(16) float2 g_wfrag[64 * NGRP * 32];

// ---------------- smem layout ----------------
#define SLABS        16
#define RING         2
#define A_ROW_F      36                     // 32 floats + 4 pad (144 B rows)
#define SLAB_BYTES   (128 * 144)            // 18432
#define BW_BYTES     (4 * NGRP * 32 * 8)    // per-slab B window = 9216
#define STAGE_BYTES  (2 * SLAB_BYTES + BW_BYTES)   // 46080
#define OFF_ENT   (RING * STAGE_BYTES)      // 92160
#define SMEM_TOTAL (OFF_ENT + 64)           // 92224 (x2 CTAs = 184448 <= 227KB)

// ---------------- PTX helpers ----------------
__device__ __forceinline__ uint32_t smem_to_u32(const void* p) {
    uint32_t a;
    asm("{ .reg .u64 t; cvta.to.shared.u64 t, %1; cvt.u32.u64 %0, t; }" : "=r"(a) : "l"(p));
    return a;
}
__device__ __forceinline__ void cpa16(uint32_t dst, const void* src) {
    asm volatile("cp.async.cg.shared.global [%0], [%1], 16;" :: "r"(dst), "l"(src) : "memory");
}
#define CP_COMMIT() asm volatile("cp.async.commit_group;" ::: "memory")
#define CP_WAIT1()  asm volatile("cp.async.wait_group 1;" ::: "memory")
#define CP_WAIT0()  asm volatile("cp.async.wait_group 0;" ::: "memory")

__device__ __forceinline__ void mma_tf32(float (&d)[4], const uint32_t (&a)[4],
                                         const uint32_t (&b)[2]) {
    asm volatile(
        "mma.sync.aligned.m16n8k8.row.col.f32.tf32.tf32.f32 "
        "{%0,%1,%2,%3}, {%4,%5,%6,%7}, {%8,%9}, {%0,%1,%2,%3};"
        : "+f"(d[0]), "+f"(d[1]), "+f"(d[2]), "+f"(d[3])
        : "r"(a[0]), "r"(a[1]), "r"(a[2]), "r"(a[3]), "r"(b[0]), "r"(b[1]));
}
__device__ __forceinline__ uint32_t to_tf32(float x) {
    uint32_t r;
    asm("cvt.rna.tf32.f32 %0, %1;" : "=r"(r) : "f"(x));
    return r;
}

// ---------------------------------------------------------------------------
// prep: pack [actor_w | critic_w] into mma B-fragment order (tf32-rounded).
// ---------------------------------------------------------------------------
__global__ void kprep(const float* __restrict__ aw, const float* __restrict__ cw) {
    int e = blockIdx.x * 256 + threadIdx.x;      // 18432 entries
    int lane = e & 31, gk = e >> 5;
    int G = gk % NGRP, ks = gk / NGRP;
    int nloc = lane >> 2;
    int k = ks * 8 + (lane & 3);
    float w0, w1;
    if (G < 8) {
        int n = G * 8 + nloc;
        w0 = aw[k * A_DIM + n];
        w1 = aw[(k + 4) * A_DIM + n];
    } else {
        w0 = (nloc == 0) ? cw[k] : 0.f;
        w1 = (nloc == 0) ? cw[k + 4] : 0.f;
    }
    float2 v;
    v.x = __uint_as_float(to_tf32(w0));
    v.y = __uint_as_float(to_tf32(w1));
    g_wfrag[e] = v;
}

// ---------------------------------------------------------------------------
// linear slab loader: L -> (tile, s). Loads states slab + next_states slab +
// per-slab B window into stage L%2.  2048 + 576 granules of 16B.
// ---------------------------------------------------------------------------
__device__ __forceinline__ void issue_slab(uint32_t su, int L,
                                           const float* __restrict__ states,
                                           const float* __restrict__ next_states,
                                           int bid, int gdim, int nb1, int tid) {
    const int tile = bid + (L >> 4) * gdim;
    if (tile >= nb1) return;
    const int s = L & 15;
    const uint32_t sbase = su + (L & 1) * STAGE_BYTES;
    const size_t goff = (size_t)tile * BM * S_DIM + s * 32;
#pragma unroll
    for (int i = 0; i < 8; ++i) {
        int g = tid + i * 256;                 // 0..2047
        int mtx = g >> 10;                     // 0: states, 1: next_states
        int r = (g & 1023) >> 3, u = g & 7;
        const float* src = (mtx ? next_states : states) + goff + (size_t)r * S_DIM + u * 4;
        cpa16(sbase + mtx * SLAB_BYTES + r * 144 + u * 16, src);
    }
    // B window: g_wfrag[(s*4)*NGRP*32 ...] -> 9216 B = 576 granules
    const char* bsrc = (const char*)(g_wfrag + (size_t)s * 4 * NGRP * 32);
    {
        int g = tid;
        cpa16(sbase + 2 * SLAB_BYTES + g * 16, bsrc + (size_t)g * 16);
        g = tid + 256;
        cpa16(sbase + 2 * SLAB_BYTES + g * 16, bsrc + (size_t)g * 16);
        if (tid < 64) {
            g = tid + 512;
            cpa16(sbase + 2 * SLAB_BYTES + g * 16, bsrc + (size_t)g * 16);
        }
    }
}

// ---------------------------------------------------------------------------
// Main fused kernel (persistent, depth-1 ring x 2 CTAs/SM)
// ---------------------------------------------------------------------------
__global__ void __launch_bounds__(256, 2)
k1_mma(const float* __restrict__ states,
       const float* __restrict__ next_states,
       const float* __restrict__ rewards,
       const int*   __restrict__ dones,
       const int*   __restrict__ actions,
       const float* __restrict__ log_probs,
       const float* __restrict__ actor_b,
       const float* __restrict__ critic_b,
       int nb1) {
    extern __shared__ __align__(16) char smem[];
    const uint32_t su = smem_to_u32(smem);
    const int tid  = threadIdx.x;
    const int w    = tid >> 5;                 // warp 0..7 -> rows 16w..16w+15
    const int lane = tid & 31;
    const int q = lane >> 2, j = lane & 3;
    const int bid = blockIdx.x, gdim = gridDim.x;

    float* sEnt = (float*)(smem + OFF_ENT);
    const float cb = critic_b[0];

    // bias for this thread's 16 actor columns: col = g*8 + j*2 + b
    float2 bias[8];
#pragma unroll
    for (int g = 0; g < 8; ++g)
        bias[g] = __ldg((const float2*)(actor_b + g * 8 + j * 2));

    // prologue: prefetch 2 stages
    issue_slab(su, 0, states, next_states, bid, gdim, nb1, tid); CP_COMMIT();
    issue_slab(su, 1, states, next_states, bid, gdim, nb1, tid); CP_COMMIT();

    for (int it = 0;; ++it) {
        const int tile = bid + it * gdim;
        if (tile >= nb1) break;
        const int row0 = tile * BM;

        float acc[8][4];     // actor groups
        float accV[4], accN[4];
#pragma unroll
        for (int g = 0; g < 8; ++g)
#pragma unroll
            for (int p = 0; p < 4; ++p) acc[g][p] = 0.f;
#pragma unroll
        for (int p = 0; p < 4; ++p) { accV[p] = 0.f; accN[p] = 0.f; }

        for (int s = 0; s < SLABS; ++s) {
            const int L = it * SLABS + s;
            CP_WAIT1();                 // group L complete (only L+1 younger)
            __syncthreads();

            const char* stage = smem + (size_t)(L & 1) * STAGE_BYTES;
            const float* Ar = (const float*)stage + (16 * w + q) * A_ROW_F + j;
            const float* Nr = (const float*)(stage + SLAB_BYTES) + (16 * w + q) * A_ROW_F + j;
            const float2* Bw = (const float2*)(stage + 2 * SLAB_BYTES);

#pragma unroll
            for (int ks = 0; ks < 4; ++ks) {
                uint32_t af[4], an[4];
                const float* Am = Ar + ks * 8;
                af[0] = __float_as_uint(Am[0]);
                af[1] = __float_as_uint(Am[8 * A_ROW_F]);
                af[2] = __float_as_uint(Am[4]);
                af[3] = __float_as_uint(Am[8 * A_ROW_F + 4]);
                const float* Nm = Nr + ks * 8;
                an[0] = __float_as_uint(Nm[0]);
                an[1] = __float_as_uint(Nm[8 * A_ROW_F]);
                an[2] = __float_as_uint(Nm[4]);
                an[3] = __float_as_uint(Nm[8 * A_ROW_F + 4]);

                const float2* Bk = Bw + (size_t)ks * NGRP * 32 + lane;
                uint32_t bfc[2];
                {
                    float2 v = Bk[8 * 32];
                    bfc[0] = __float_as_uint(v.x);
                    bfc[1] = __float_as_uint(v.y);
                }
#pragma unroll
                for (int g = 0; g < 8; ++g) {
                    uint32_t bf[2];
                    float2 v = Bk[g * 32];
                    bf[0] = __float_as_uint(v.x);
                    bf[1] = __float_as_uint(v.y);
                    mma_tf32(acc[g], af, bf);
                }
                mma_tf32(accV, af, bfc);   // values
                mma_tf32(accN, an, bfc);   // next_values
            }
            __syncthreads();            // stage (L&1) fully consumed
            issue_slab(su, L + 2, states, next_states, bid, gdim, nb1, tid);
            CP_COMMIT();
        }

        // ---- register epilogue: rows 16w+q (half 0) and 16w+q+8 (half 1) ----
        float ent2 = 0.f;
#pragma unroll
        for (int half = 0; half < 2; ++half) {
            float tl[8][2];
            float m = -1e30f;
#pragma unroll
            for (int g = 0; g < 8; ++g) {
                tl[g][0] = acc[g][half * 2]     + bias[g].x;
                tl[g][1] = acc[g][half * 2 + 1] + bias[g].y;
                m = fmaxf(m, fmaxf(tl[g][0], tl[g][1]));
            }
            m = fmaxf(m, __shfl_xor_sync(0xffffffffu, m, 1));
            m = fmaxf(m, __shfl_xor_sync(0xffffffffu, m, 2));

            float se = 0.f, pe = 0.f;
#pragma unroll
            for (int g = 0; g < 8; ++g) {
#pragma unroll
                for (int b = 0; b < 2; ++b) {
                    float t = tl[g][b] - m;
                    tl[g][b] = t;
                    float e = __expf(t);
                    se += e;
                    pe = fmaf(e, t, pe);
                }
            }
            se += __shfl_xor_sync(0xffffffffu, se, 1);
            se += __shfl_xor_sync(0xffffffffu, se, 2);
            pe += __shfl_xor_sync(0xffffffffu, pe, 1);
            pe += __shfl_xor_sync(0xffffffffu, pe, 2);

            const int r = 16 * w + q + half * 8;
            const int grow = row0 + r;
            const int a = __ldg(actions + grow);
            float cand = -1e30f;
            if (j == ((a >> 1) & 3)) {
                const int ga = a >> 3, ba = a & 1;
#pragma unroll
                for (int g = 0; g < 8; ++g)
                    if (g == ga) cand = ba ? tl[g][1] : tl[g][0];
            }
            cand = fmaxf(cand, __shfl_xor_sync(0xffffffffu, cand, 1));
            cand = fmaxf(cand, __shfl_xor_sync(0xffffffffu, cand, 2));

            if (j == 0) {
                const float logse = __logf(se);
                const float ratio = __expf(cand - logse - __ldg(log_probs + grow));
                const float nd = 1.f - (float)__ldg(dones + grow);
                const float v  = accV[half * 2] + cb;
                const float nv = accN[half * 2] + cb;
                g_delta[grow] = __ldg(rewards + grow) + GAMMA_F * nv * nd - v;
                g_ratio[grow] = ratio;
                ent2 += logse - pe / se;
            }
        }
#pragma unroll
        for (int o = 16; o > 0; o >>= 1) ent2 += __shfl_xor_sync(0xffffffffu, ent2, o);
        if (lane == 0) sEnt[w] = ent2;
        __syncthreads();
        if (tid == 0) {
            float s8 = 0.f;
#pragma unroll
            for (int i = 0; i < 8; ++i) s8 += sEnt[i];
            g_ent[tile] = s8;
        }
    }
    CP_WAIT0();
}

// ---------------------------------------------------------------------------
// GAE scan
// ---------------------------------------------------------------------------
__device__ __forceinline__ void thread_affine(const int* __restrict__ dones,
                                              int base, float (&d)[8], float (&c)[8],
                                              float& A, float& Bv) {
    float4 d0 = *(const float4*)&g_delta[base];
    float4 d1 = *(const float4*)&g_delta[base + 4];
    int4 q0 = *(const int4*)&dones[base];
    int4 q1 = *(const int4*)&dones[base + 4];
    d[0]=d0.x; d[1]=d0.y; d[2]=d0.z; d[3]=d0.w;
    d[4]=d1.x; d[5]=d1.y; d[6]=d1.z; d[7]=d1.w;
    c[0]=GL_F*(1.f-(float)q0.x); c[1]=GL_F*(1.f-(float)q0.y);
    c[2]=GL_F*(1.f-(float)q0.z); c[3]=GL_F*(1.f-(float)q0.w);
    c[4]=GL_F*(1.f-(float)q1.x); c[5]=GL_F*(1.f-(float)q1.y);
    c[6]=GL_F*(1.f-(float)q1.z); c[7]=GL_F*(1.f-(float)q1.w);
    A = 1.f; Bv = 0.f;
#pragma unroll
    for (int jj = 7; jj >= 0; --jj) { Bv = fmaf(c[jj], Bv, d[jj]); A = c[jj] * A; }
}

__global__ void __launch_bounds__(256)
k2_chunk_reduce(const int* __restrict__ dones) {
    __shared__ float sa[256], sb[256];
    const int tid = threadIdx.x;
    const int base = blockIdx.x * CHUNK + tid * 8;
    float d[8], c[8], A, Bv;
    thread_affine(dones, base, d, c, A, Bv);
    sa[tid] = A; sb[tid] = Bv;
    __syncthreads();
    for (int s = 1; s < 256; s <<= 1) {
        if ((tid & (2 * s - 1)) == 0) {
            float al = sa[tid], bl = sb[tid];
            float ar = sa[tid + s], br = sb[tid + s];
            sa[tid] = al * ar;
            sb[tid] = fmaf(al, br, bl);
        }
        __syncthreads();
    }
    if (tid == 0) { g_cA[blockIdx.x] = sa[0]; g_cB[blockIdx.x] = sb[0]; }
}

__global__ void __launch_bounds__(256)
k4_apply(const int* __restrict__ dones, int nb) {
    __shared__ float sa[256], sb[256];
    __shared__ float ca[NB_MAX], cbv[NB_MAX];
    const int tid = threadIdx.x;

    if (tid < NB_MAX) { ca[tid] = g_cA[tid]; cbv[tid] = g_cB[tid]; }
    __syncthreads();
    for (int dd = 1; dd < NB_MAX; dd <<= 1) {
        float a = 0.f, b = 0.f, ar = 1.f, br = 0.f;
        if (tid < NB_MAX) {
            a = ca[tid]; b = cbv[tid];
            if (tid + dd < NB_MAX) { ar = ca[tid + dd]; br = cbv[tid + dd]; }
        }
        __syncthreads();
        if (tid < NB_MAX) { ca[tid] = a * ar; cbv[tid] = fmaf(a, br, b); }
        __syncthreads();
    }
    const int blk = blockIdx.x;
    const float xb = (blk + 1 < nb) ? cbv[blk + 1] : 0.f;

    const int base = blk * CHUNK + tid * 8;
    float d[8], c[8], A, Bv;
    thread_affine(dones, base, d, c, A, Bv);
    sa[tid] = A; sb[tid] = Bv;
    __syncthreads();
    for (int dd = 1; dd < 256; dd <<= 1) {
        float al = sa[tid], bl = sb[tid];
        float ar = 1.f, br = 0.f;
        if (tid + dd < 256) { ar = sa[tid + dd]; br = sb[tid + dd]; }
        __syncthreads();
        sa[tid] = al * ar;
        sb[tid] = fmaf(al, br, bl);
        __syncthreads();
    }
    float xin = (tid == 255) ? xb : fmaf(sa[tid + 1], xb, sb[tid + 1]);

    float4 r0 = *(const float4*)&g_ratio[base];
    float4 r1 = *(const float4*)&g_ratio[base + 4];
    float rt[8] = {r0.x, r0.y, r0.z, r0.w, r1.x, r1.y, r1.z, r1.w};

    float adv = xin, s1 = 0.f, s2 = 0.f;
#pragma unroll
    for (int jj = 7; jj >= 0; --jj) {
        adv = fmaf(c[jj], adv, d[jj]);
        const float r = rt[jj];
        const float rc = fminf(fmaxf(r, CLIP_LO), CLIP_HI);
        s1 += fminf(r * adv, rc * adv);
        s2 = fmaf(adv, adv, s2);
    }
    __syncthreads();
    sa[tid] = s1; sb[tid] = s2;
    __syncthreads();
    for (int s = 128; s > 0; s >>= 1) {
        if (tid < s) { sa[tid] += sa[tid + s]; sb[tid] += sb[tid + s]; }
        __syncthreads();
    }
    if (tid == 0) { g_surr[blk] = sa[0]; g_adv2[blk] = sb[0]; }
}

__global__ void __launch_bounds__(256)
k5_final(float* __restrict__ out, int T, int nb, int nb1) {
    __shared__ float se_[256], ss_[256], sv_[256];
    const int tid = threadIdx.x;
    float e = 0.f, s = 0.f, v = 0.f;
    for (int i = tid; i < nb1; i += 256) e += g_ent[i];
    for (int i = tid; i < nb; i += 256) { s += g_surr[i]; v += g_adv2[i]; }
    se_[tid] = e; ss_[tid] = s; sv_[tid] = v;
    __syncthreads();
    for (int st = 128; st > 0; st >>= 1) {
        if (tid < st) {
            se_[tid] += se_[tid + st];
            ss_[tid] += ss_[tid + st];
            sv_[tid] += sv_[tid + st];
        }
        __syncthreads();
    }
    if (tid == 0) {
        const float invT = 1.f / (float)T;
        out[0] = -(ss_[0] * invT) - ENT_C * (se_[0] * invT);
        out[1] = sv_[0] * invT;
    }
}

extern "C" void kernel_launch(void* const* d_in, const int* in_sizes, int n_in,
                              void* d_out, int out_size) {
    const float* states      = (const float*)d_in[0];
    const float* next_states = (const float*)d_in[1];
    const float* rewards     = (const float*)d_in[2];
    const int*   dones       = (const int*)  d_in[3];
    const int*   actions     = (const int*)  d_in[4];
    const float* log_probs   = (const float*)d_in[5];
    const float* actor_w     = (const float*)d_in[6];
    const float* actor_b     = (const float*)d_in[7];
    const float* critic_w    = (const float*)d_in[8];
    const float* critic_b    = (const float*)d_in[9];
    float* out = (float*)d_out;

    const int T   = in_sizes[2];
    const int nb1 = T / BM;       // 2048
    const int nb  = T / CHUNK;    // 128
    const int grid1 = nb1 < GRID1 ? nb1 : GRID1;

    cudaFuncSetAttribute(k1_mma, cudaFuncAttributeMaxDynamicSharedMemorySize, SMEM_TOTAL);

    kprep<<<(64 * NGRP * 32) / 256, 256>>>(actor_w, critic_w);
    k1_mma<<<grid1, 256, SMEM_TOTAL>>>(states, next_states, rewards, dones, actions,
                                       log_probs, actor_b, critic_b, nb1);
    k2_chunk_reduce<<<nb, 256>>>(dones);
    k4_apply<<<nb, 256>>>(dones, nb);
    k5_final<<<1, 256>>>(out, T, nb, nb1);
}